// round 12
// baseline (speedup 1.0000x reference)
#include <cuda_runtime.h>
#include <cuda_fp16.h>
#include <cstdint>

#define SPARSITY 0.01f
#define BATCH 8
#define NN    2048
#define DIN   256
#define DOUT  256

__device__ __half g_SUP[BATCH * NN * DOUT];  // support fp16: [b*node][col]

__device__ __forceinline__ uint32_t smem_u32(const void* p) {
    uint32_t a;
    asm("{ .reg .u64 t; cvta.to.shared.u64 t, %1; cvt.u32.u64 %0, t; }"
        : "=r"(a) : "l"(p));
    return a;
}

// ---------------- mma helpers -----------------------------------------------
#define TK 32
__device__ __forceinline__ uint32_t swz16(int row, int c) {
    return (uint32_t)(row * 64 + ((c ^ ((row >> 1) & 3)) << 4));
}
__device__ __forceinline__ void ldsm4(uint32_t& r0, uint32_t& r1, uint32_t& r2,
                                      uint32_t& r3, uint32_t addr) {
    asm volatile("ldmatrix.sync.aligned.m8n8.x4.shared.b16 {%0,%1,%2,%3}, [%4];"
                 : "=r"(r0), "=r"(r1), "=r"(r2), "=r"(r3) : "r"(addr));
}
__device__ __forceinline__ void ldsm4t(uint32_t& r0, uint32_t& r1, uint32_t& r2,
                                       uint32_t& r3, uint32_t addr) {
    asm volatile("ldmatrix.sync.aligned.m8n8.x4.trans.shared.b16 {%0,%1,%2,%3}, [%4];"
                 : "=r"(r0), "=r"(r1), "=r"(r2), "=r"(r3) : "r"(addr));
}
__device__ __forceinline__ void mma_f16(float* d, uint32_t a0, uint32_t a1,
                                        uint32_t a2, uint32_t a3,
                                        uint32_t b0, uint32_t b1) {
    asm volatile(
        "mma.sync.aligned.m16n8k16.row.col.f32.f16.f16.f32 "
        "{%0,%1,%2,%3}, {%4,%5,%6,%7}, {%8,%9}, {%0,%1,%2,%3};"
        : "+f"(d[0]), "+f"(d[1]), "+f"(d[2]), "+f"(d[3])
        : "r"(a0), "r"(a1), "r"(a2), "r"(a3), "r"(b0), "r"(b1));
}
__device__ __forceinline__ void cpasync16(uint32_t dst, const void* src) {
    asm volatile("cp.async.cg.shared.global [%0], [%1], 16;" :: "r"(dst), "l"(src));
}

#define A_TILE  8192                          // 128 x 32 fp16

// ============================================================================
// GEMM1 (fused quantize): SUP = (x @ quantize(W)) * s, fp16 out.
// M=16384, N=256, K=256.  CTA 128x256, grid=128, 1 CTA/SM.
// B = quant(W) held ENTIRELY in smem (256 k-rows x 512B, trans-ldsm layout),
// built once per CTA from fp32 W (L2-resident). A: fp32 LDG->cvt->STS, 2-slot.
// ============================================================================
#define G1_B  (DIN * 512)                     // 131072
#define G1_SM (G1_B + 2 * A_TILE)             // 147456

__global__ void __launch_bounds__(256, 1) gemm1_kernel(
    const float* __restrict__ x,     // [16384, 256]
    const float* __restrict__ W,     // [256(k), 256(n)] row-major
    __half* __restrict__ SUP)        // [16384, 256] fp16
{
    extern __shared__ char smem[];
    const uint32_t sb = smem_u32(smem);
    const int t = threadIdx.x, wid = t >> 5, lane = t & 31;
    const int bm = blockIdx.x * 128;

    const int M0 = (wid & 1) * 64;
    const int N0 = (wid >> 1) * 64;
    const uint32_t sA0 = sb + G1_B;

    // ---- build B = quant(W) in smem, trans-ldsm layout ----
    #pragma unroll
    for (int i = 0; i < 32; i++) {
        int c = t + 256 * i;                 // 16B-chunk id 0..8191
        int k = c >> 5, nch = c & 31;
        const float* p = W + (size_t)k * DOUT + (nch << 3);
        float4 v0 = *(const float4*)p;
        float4 v1 = *(const float4*)(p + 4);
        __half h[8];
        const float* vv = (const float*)&v0;
        #pragma unroll
        for (int j = 0; j < 8; j++) {
            float w = (j < 4) ? vv[j] : ((const float*)&v1)[j - 4];
            h[j] = __float2half_rn((w > SPARSITY ? 1.0f : 0.0f) +
                                   (w < -SPARSITY ? -1.0f : 0.0f));
        }
        *(uint4*)(smem + k * 512 + ((nch ^ (k & 7)) << 4)) = *(const uint4*)h;
    }

    float acc[4][8][4] = {};
    float4 areg[2][2];

    auto ldgA = [&](int it) {
        const int k0 = it * TK;
        #pragma unroll
        for (int s = 0; s < 2; s++) {
            int m = t + 256 * s;
            int r = m >> 2, c = m & 3;
            const float* p = x + (size_t)(bm + r) * DIN + k0 + (c << 3);
            areg[s][0] = *(const float4*)p;
            areg[s][1] = *(const float4*)(p + 4);
        }
    };
    auto stsA = [&](int slot) {
        #pragma unroll
        for (int s = 0; s < 2; s++) {
            int m = t + 256 * s;
            int r = m >> 2, c = m & 3;
            __half2 h[4];
            h[0] = __floats2half2_rn(areg[s][0].x, areg[s][0].y);
            h[1] = __floats2half2_rn(areg[s][0].z, areg[s][0].w);
            h[2] = __floats2half2_rn(areg[s][1].x, areg[s][1].y);
            h[3] = __floats2half2_rn(areg[s][1].z, areg[s][1].w);
            *(uint4*)(smem + G1_B + slot * A_TILE + swz16(r, c)) = *(const uint4*)h;
        }
    };

    // ---- prologue ----
    ldgA(0);
    stsA(0);
    ldgA(1);
    __syncthreads();

    const int g = lane >> 3, l7 = lane & 7;
    const int KITERS = DIN / TK;   // 8

    for (int it = 0; it < KITERS; it++) {
        stsA((it + 1) & 1);
        ldgA(min(it + 2, KITERS - 1));

        const uint32_t abase = sA0 + (it & 1) * A_TILE;

        #pragma unroll
        for (int ks = 0; ks < 2; ks++) {
            uint32_t a[4][4];
            #pragma unroll
            for (int mf = 0; mf < 4; mf++) {
                int row = M0 + mf * 16 + ((g & 1) << 3) + l7;
                int ch  = ks * 2 + (g >> 1);
                ldsm4(a[mf][0], a[mf][1], a[mf][2], a[mf][3], abase + swz16(row, ch));
            }
            uint32_t bf[8][2];
            #pragma unroll
            for (int j8 = 0; j8 < 4; j8++) {
                int krow = it * TK + ks * 16 + ((g & 1) << 3) + l7;  // 0..255
                int nch  = ((N0 + j8 * 16) >> 3) + (g >> 1);
                uint32_t r0, r1, r2, r3;
                ldsm4t(r0, r1, r2, r3,
                       sb + krow * 512 + ((nch ^ (krow & 7)) << 4));
                bf[j8 * 2][0] = r0; bf[j8 * 2][1] = r1;
                bf[j8 * 2 + 1][0] = r2; bf[j8 * 2 + 1][1] = r3;
            }
            #pragma unroll
            for (int mf = 0; mf < 4; mf++)
                #pragma unroll
                for (int nf = 0; nf < 8; nf++)
                    mma_f16(acc[mf][nf], a[mf][0], a[mf][1], a[mf][2], a[mf][3],
                            bf[nf][0], bf[nf][1]);
        }
        __syncthreads();
    }

    // ---- epilogue: * SPARSITY -> fp16 ----
    const int rq = lane >> 2, cq = lane & 3;
    #pragma unroll
    for (int nf = 0; nf < 8; nf++) {
        const int col = N0 + nf * 8 + (cq << 1);
        #pragma unroll
        for (int mf = 0; mf < 4; mf++) {
            const int row = bm + M0 + mf * 16 + rq;
            __half* o0 = SUP + (size_t)row * DOUT + col;
            *(__half2*)o0 =
                __floats2half2_rn(acc[mf][nf][0] * SPARSITY,
                                  acc[mf][nf][1] * SPARSITY);
            *(__half2*)(o0 + 8 * (size_t)DOUT) =
                __floats2half2_rn(acc[mf][nf][2] * SPARSITY,
                                  acc[mf][nf][3] * SPARSITY);
        }
    }
}

// ============================================================================
// GEMM2: out[b] = relu(adj[b] @ SUP[b] + bias).  M=2048, N=256, K=2048.
// CTA 128x256x32, grid=128 (single wave). B [k][n] via trans-ldsm, 4-stage.
// A: fp32 LDG -> cvt -> STS, double-buffered.  (round-9 code, at HMMA wall)
// ============================================================================
#define B_STAGE 16384
#define G2_SM   (4 * B_STAGE + 2 * A_TILE)    // 81920

__global__ void __launch_bounds__(256, 1) gemm2_kernel(
    const float* __restrict__ adj,
    const __half* __restrict__ SUP,
    const float* __restrict__ bias,
    float* __restrict__ out)
{
    extern __shared__ char smem[];
    const uint32_t sb = smem_u32(smem);
    const int t = threadIdx.x, wid = t >> 5, lane = t & 31;
    const int bm = blockIdx.x * 128;
    const int b  = blockIdx.y;

    const float*  Ag = adj + (size_t)b * NN * NN;
    const __half* Bg = SUP + (size_t)b * NN * DOUT;

    const int M0 = (wid & 1) * 64;
    const int N0 = (wid >> 1) * 64;

    const uint32_t sB0 = sb;
    const uint32_t sA0 = sb + 4 * B_STAGE;

    float acc[4][8][4] = {};
    float4 areg[2][2];

    auto loadB = [&](int it, int slot) {
        const int k0 = it * TK;
        const uint32_t s0 = sB0 + slot * B_STAGE;
        #pragma unroll
        for (int i = 0; i < 4; i++) {
            int c = t + 256 * i;                    // 0..1023
            int k = c >> 5, nch = c & 31;
            cpasync16(s0 + k * 512 + ((nch ^ (k & 7)) << 4),
                      Bg + (size_t)(k0 + k) * DOUT + (nch << 3));
        }
        asm volatile("cp.async.commit_group;");
    };
    auto ldgA = [&](int it) {
        const int k0 = it * TK;
        #pragma unroll
        for (int s = 0; s < 2; s++) {
            int m = t + 256 * s;
            int r = m >> 2, c = m & 3;
            const float* p = Ag + (size_t)(bm + r) * NN + k0 + (c << 3);
            areg[s][0] = *(const float4*)p;
            areg[s][1] = *(const float4*)(p + 4);
        }
    };
    auto stsA = [&](int slot) {
        #pragma unroll
        for (int s = 0; s < 2; s++) {
            int m = t + 256 * s;
            int r = m >> 2, c = m & 3;
            __half2 h[4];
            h[0] = __floats2half2_rn(areg[s][0].x, areg[s][0].y);
            h[1] = __floats2half2_rn(areg[s][0].z, areg[s][0].w);
            h[2] = __floats2half2_rn(areg[s][1].x, areg[s][1].y);
            h[3] = __floats2half2_rn(areg[s][1].z, areg[s][1].w);
            *(uint4*)(smem + 4 * B_STAGE + slot * A_TILE + swz16(r, c)) =
                *(const uint4*)h;
        }
    };

    const int KITERS = NN / TK;   // 64

    // ---- prologue ----
    ldgA(0);
    loadB(0, 0);
    loadB(1, 1);
    loadB(2, 2);
    stsA(0);
    ldgA(1);
    asm volatile("cp.async.wait_group 2;");
    __syncthreads();

    const int g = lane >> 3, l7 = lane & 7;

    for (int it = 0; it < KITERS; it++) {
        if (it + 3 < KITERS) loadB(it + 3, (it + 3) & 3);
        else asm volatile("cp.async.commit_group;");

        stsA((it + 1) & 1);
        ldgA(min(it + 2, KITERS - 1));

        const uint32_t abase = sA0 + (it & 1) * A_TILE;
        const uint32_t bbase = sB0 + (it & 3) * B_STAGE;

        #pragma unroll
        for (int ks = 0; ks < 2; ks++) {
            uint32_t a[4][4];
            #pragma unroll
            for (int mf = 0; mf < 4; mf++) {
                int row = M0 + mf * 16 + ((g & 1) << 3) + l7;
                int ch  = ks * 2 + (g >> 1);
                ldsm4(a[mf][0], a[mf][1], a[mf][2], a[mf][3], abase + swz16(row, ch));
            }
            uint32_t bf[8][2];
            #pragma unroll
            for (int j8 = 0; j8 < 4; j8++) {
                int kl  = ks * 16 + ((g & 1) << 3) + l7;
                int nch = ((N0 + j8 * 16) >> 3) + (g >> 1);
                uint32_t r0, r1, r2, r3;
                ldsm4t(r0, r1, r2, r3,
                       bbase + kl * 512 + ((nch ^ (kl & 7)) << 4));
                bf[j8 * 2][0] = r0; bf[j8 * 2][1] = r1;
                bf[j8 * 2 + 1][0] = r2; bf[j8 * 2 + 1][1] = r3;
            }
            #pragma unroll
            for (int mf = 0; mf < 4; mf++)
                #pragma unroll
                for (int nf = 0; nf < 8; nf++)
                    mma_f16(acc[mf][nf], a[mf][0], a[mf][1], a[mf][2], a[mf][3],
                            bf[nf][0], bf[nf][1]);
        }

        asm volatile("cp.async.wait_group 2;");
        __syncthreads();
    }

    // ---- epilogue: bias + relu ----
    const int rq = lane >> 2, cq = lane & 3;
    float* Cg = out + (size_t)b * NN * DOUT;
    #pragma unroll
    for (int nf = 0; nf < 8; nf++) {
        const int col = N0 + nf * 8 + (cq << 1);
        const float2 bv = *(const float2*)(bias + col);
        #pragma unroll
        for (int mf = 0; mf < 4; mf++) {
            const int row = bm + M0 + mf * 16 + rq;
            float* o0 = Cg + (size_t)row * DOUT + col;
            float2 v0, v1;
            v0.x = fmaxf(acc[mf][nf][0] + bv.x, 0.0f);
            v0.y = fmaxf(acc[mf][nf][1] + bv.y, 0.0f);
            v1.x = fmaxf(acc[mf][nf][2] + bv.x, 0.0f);
            v1.y = fmaxf(acc[mf][nf][3] + bv.y, 0.0f);
            *(float2*)o0 = v0;
            *(float2*)(o0 + 8 * DOUT) = v1;
        }
    }
}

// ============================================================================
extern "C" void kernel_launch(void* const* d_in, const int* in_sizes, int n_in,
                              void* d_out, int out_size) {
    const float* x      = (const float*)d_in[0];
    const float* adj    = (const float*)d_in[1];
    const float* weight = (const float*)d_in[2];
    const float* bias   = (const float*)d_in[3];
    float* out = (float*)d_out;

    __half* SUP;
    cudaGetSymbolAddress((void**)&SUP, g_SUP);

    // 1) SUP = (x @ quantize(W)) * s   (quantization fused; W read from L2)
    {
        cudaFuncSetAttribute(gemm1_kernel,
                             cudaFuncAttributeMaxDynamicSharedMemorySize, G1_SM);
        gemm1_kernel<<<(BATCH * NN) / 128, 256, G1_SM>>>(x, weight, SUP);
    }
    // 2) out[b] = relu(adj[b] @ SUP[b] + bias)
    {
        cudaFuncSetAttribute(gemm2_kernel,
                             cudaFuncAttributeMaxDynamicSharedMemorySize, G2_SM);
        dim3 grid(NN / 128, BATCH, 1);
        gemm2_kernel<<<grid, 256, G2_SM>>>(adj, SUP, bias, out);
    }
}

// round 13
// speedup vs baseline: 1.3837x; 1.3837x over previous
#include <cuda_runtime.h>
#include <cuda_fp16.h>
#include <cstdint>

#define SPARSITY 0.01f
#define BATCH 8
#define NN    2048
#define DIN   256
#define DOUT  256

__device__ __half g_SUP[BATCH * NN * DOUT];  // support fp16: [b*node][col]

__device__ __forceinline__ uint32_t smem_u32(const void* p) {
    uint32_t a;
    asm("{ .reg .u64 t; cvta.to.shared.u64 t, %1; cvt.u32.u64 %0, t; }"
        : "=r"(a) : "l"(p));
    return a;
}

// ---------------- mma helpers -----------------------------------------------
#define TK 32
__device__ __forceinline__ uint32_t swz16(int row, int c) {
    return (uint32_t)(row * 64 + ((c ^ ((row >> 1) & 3)) << 4));
}
__device__ __forceinline__ void ldsm4(uint32_t& r0, uint32_t& r1, uint32_t& r2,
                                      uint32_t& r3, uint32_t addr) {
    asm volatile("ldmatrix.sync.aligned.m8n8.x4.shared.b16 {%0,%1,%2,%3}, [%4];"
                 : "=r"(r0), "=r"(r1), "=r"(r2), "=r"(r3) : "r"(addr));
}
__device__ __forceinline__ void ldsm4t(uint32_t& r0, uint32_t& r1, uint32_t& r2,
                                       uint32_t& r3, uint32_t addr) {
    asm volatile("ldmatrix.sync.aligned.m8n8.x4.trans.shared.b16 {%0,%1,%2,%3}, [%4];"
                 : "=r"(r0), "=r"(r1), "=r"(r2), "=r"(r3) : "r"(addr));
}
__device__ __forceinline__ void mma_f16(float* d, uint32_t a0, uint32_t a1,
                                        uint32_t a2, uint32_t a3,
                                        uint32_t b0, uint32_t b1) {
    asm volatile(
        "mma.sync.aligned.m16n8k16.row.col.f32.f16.f16.f32 "
        "{%0,%1,%2,%3}, {%4,%5,%6,%7}, {%8,%9}, {%0,%1,%2,%3};"
        : "+f"(d[0]), "+f"(d[1]), "+f"(d[2]), "+f"(d[3])
        : "r"(a0), "r"(a1), "r"(a2), "r"(a3), "r"(b0), "r"(b1));
}
__device__ __forceinline__ void cpasync16(uint32_t dst, const void* src) {
    asm volatile("cp.async.cg.shared.global [%0], [%1], 16;" :: "r"(dst), "l"(src));
}

#define B_STAGE 16384
#define A_TILE  8192
#define G_SM    (4 * B_STAGE + 2 * A_TILE)    // 81920

// ============================================================================
// Round-9 template, VERBATIM (runtime strides — do not constant-fold; the
// compile-time-stride variant compiles to 232 regs and runs 1.5x slower).
// Used here only as GEMM2: TRANSB=1, RELU=1.
// ============================================================================
template<int KITERS, bool TRANSB, bool RELU>
__global__ void __launch_bounds__(256, 1) mm_kernel(
    const float* __restrict__ Abase, size_t strideA, int lda,
    const __half* __restrict__ Bbase, size_t strideB, int ldb,
    void* __restrict__ Cbase, size_t strideC, int ldc,
    const float* __restrict__ bias)
{
    extern __shared__ char smem[];
    const uint32_t sb = smem_u32(smem);
    const int t = threadIdx.x, wid = t >> 5, lane = t & 31;
    const int bm = blockIdx.x * 128;
    const int b  = blockIdx.y;

    const float*  Ag = Abase + (size_t)b * strideA;
    const __half* Bg = Bbase + (size_t)b * strideB;

    const int M0 = (wid & 1) * 64;
    const int N0 = (wid >> 1) * 64;

    const uint32_t sB0 = sb;
    const uint32_t sA0 = sb + 4 * B_STAGE;

    float acc[4][8][4] = {};
    float4 areg[2][2];

    auto loadB = [&](int it, int slot) {
        const int k0 = it * TK;
        const uint32_t s0 = sB0 + slot * B_STAGE;
        #pragma unroll
        for (int i = 0; i < 4; i++) {
            int c = t + 256 * i;
            if (TRANSB) {
                int k = c >> 5, nch = c & 31;
                cpasync16(s0 + k * 512 + ((nch ^ (k & 7)) << 4),
                          Bg + (size_t)(k0 + k) * ldb + (nch << 3));
            } else {
                int r = c >> 2, ch = c & 3;
                cpasync16(s0 + swz16(r, ch),
                          Bg + (size_t)r * ldb + k0 + (ch << 3));
            }
        }
        asm volatile("cp.async.commit_group;");
    };
    auto ldgA = [&](int it) {
        const int k0 = it * TK;
        #pragma unroll
        for (int s = 0; s < 2; s++) {
            int m = t + 256 * s;
            int r = m >> 2, c = m & 3;
            const float* p = Ag + (size_t)(bm + r) * lda + k0 + (c << 3);
            areg[s][0] = *(const float4*)p;
            areg[s][1] = *(const float4*)(p + 4);
        }
    };
    auto stsA = [&](int slot) {
        #pragma unroll
        for (int s = 0; s < 2; s++) {
            int m = t + 256 * s;
            int r = m >> 2, c = m & 3;
            __half2 h[4];
            h[0] = __floats2half2_rn(areg[s][0].x, areg[s][0].y);
            h[1] = __floats2half2_rn(areg[s][0].z, areg[s][0].w);
            h[2] = __floats2half2_rn(areg[s][1].x, areg[s][1].y);
            h[3] = __floats2half2_rn(areg[s][1].z, areg[s][1].w);
            *(uint4*)(smem + 4 * B_STAGE + slot * A_TILE + swz16(r, c)) =
                *(const uint4*)h;
        }
    };

    // ---- prologue ----
    ldgA(0);
    loadB(0, 0);
    loadB(1, 1);
    loadB(2, 2);
    stsA(0);
    ldgA(1);
    asm volatile("cp.async.wait_group 2;");
    __syncthreads();

    const int g = lane >> 3, l7 = lane & 7;

    for (int it = 0; it < KITERS; it++) {
        if (it + 3 < KITERS) loadB(it + 3, (it + 3) & 3);
        else asm volatile("cp.async.commit_group;");

        stsA((it + 1) & 1);
        ldgA(min(it + 2, KITERS - 1));

        const uint32_t abase = sA0 + (it & 1) * A_TILE;
        const uint32_t bbase = sB0 + (it & 3) * B_STAGE;

        #pragma unroll
        for (int ks = 0; ks < 2; ks++) {
            uint32_t a[4][4];
            #pragma unroll
            for (int mf = 0; mf < 4; mf++) {
                int row = M0 + mf * 16 + ((g & 1) << 3) + l7;
                int ch  = ks * 2 + (g >> 1);
                ldsm4(a[mf][0], a[mf][1], a[mf][2], a[mf][3], abase + swz16(row, ch));
            }
            uint32_t bf[8][2];
            #pragma unroll
            for (int j8 = 0; j8 < 4; j8++) {
                uint32_t r0, r1, r2, r3;
                if (TRANSB) {
                    int kl  = ks * 16 + ((g & 1) << 3) + l7;
                    int nch = ((N0 + j8 * 16) >> 3) + (g >> 1);
                    ldsm4t(r0, r1, r2, r3,
                           bbase + kl * 512 + ((nch ^ (kl & 7)) << 4));
                } else {
                    int row = N0 + j8 * 16 + ((g >> 1) << 3) + l7;
                    int ch  = ks * 2 + (g & 1);
                    ldsm4(r0, r1, r2, r3, bbase + swz16(row, ch));
                }
                bf[j8 * 2][0] = r0; bf[j8 * 2][1] = r1;
                bf[j8 * 2 + 1][0] = r2; bf[j8 * 2 + 1][1] = r3;
            }
            #pragma unroll
            for (int mf = 0; mf < 4; mf++)
                #pragma unroll
                for (int nf = 0; nf < 8; nf++)
                    mma_f16(acc[mf][nf], a[mf][0], a[mf][1], a[mf][2], a[mf][3],
                            bf[nf][0], bf[nf][1]);
        }

        asm volatile("cp.async.wait_group 2;");
        __syncthreads();
    }

    // ---- epilogue ----
    const int rq = lane >> 2, cq = lane & 3;
    #pragma unroll
    for (int nf = 0; nf < 8; nf++) {
        const int col = N0 + nf * 8 + (cq << 1);
        float2 bv = make_float2(0.f, 0.f);
        if (RELU) bv = *(const float2*)(bias + col);
        #pragma unroll
        for (int mf = 0; mf < 4; mf++) {
            const int row = bm + M0 + mf * 16 + rq;
            if (RELU) {
                float* Cg = (float*)Cbase + (size_t)b * strideC;
                float* o0 = Cg + (size_t)row * ldc + col;
                float2 v0, v1;
                v0.x = fmaxf(acc[mf][nf][0] + bv.x, 0.0f);
                v0.y = fmaxf(acc[mf][nf][1] + bv.y, 0.0f);
                v1.x = fmaxf(acc[mf][nf][2] + bv.x, 0.0f);
                v1.y = fmaxf(acc[mf][nf][3] + bv.y, 0.0f);
                *(float2*)o0 = v0;
                *(float2*)(o0 + 8 * (size_t)ldc) = v1;
            } else {
                __half* Cg = (__half*)Cbase + (size_t)b * strideC;
                __half* o0 = Cg + (size_t)row * ldc + col;
                *(__half2*)o0 =
                    __floats2half2_rn(acc[mf][nf][0] * SPARSITY,
                                      acc[mf][nf][1] * SPARSITY);
                *(__half2*)(o0 + 8 * (size_t)ldc) =
                    __floats2half2_rn(acc[mf][nf][2] * SPARSITY,
                                      acc[mf][nf][3] * SPARSITY);
            }
        }
    }
}

// ============================================================================
// GEMM1 fused: SUP = (x @ quantize(W)) * s.  M=16384, N=256, K=256.
// W quantized into smem once per CTA (low-unroll build loop, L2-served),
// then the proven A-convert mainloop (runtime lda to keep codegen lean).
// ============================================================================
#define G1_B  (DIN * 512)                     // 131072
#define G1_SM (G1_B + 2 * A_TILE)             // 147456

__global__ void __launch_bounds__(256, 1) gemm1_kernel(
    const float* __restrict__ x, int lda,     // [16384, lda=256]
    const float* __restrict__ W, int ldw,     // [256(k), ldw=256(n)]
    __half* __restrict__ SUP, int ldc)        // [16384, ldc=256] fp16
{
    extern __shared__ char smem[];
    const uint32_t sb = smem_u32(smem);
    const int t = threadIdx.x, wid = t >> 5, lane = t & 31;
    const int bm = blockIdx.x * 128;

    const int M0 = (wid & 1) * 64;
    const int N0 = (wid >> 1) * 64;
    const uint32_t sA0 = sb + G1_B;

    // ---- build B = quant(W) in smem, trans-ldsm layout (low unroll) ----
    #pragma unroll 2
    for (int c = t; c < 8192; c += 256) {     // 16B fp16 chunks
        int k = c >> 5, nch = c & 31;
        const float* p = W + (size_t)k * ldw + (nch << 3);
        float4 v0 = *(const float4*)p;
        float4 v1 = *(const float4*)(p + 4);
        float vv[8] = {v0.x, v0.y, v0.z, v0.w, v1.x, v1.y, v1.z, v1.w};
        __half h[8];
        #pragma unroll
        for (int j = 0; j < 8; j++)
            h[j] = __float2half_rn((vv[j] > SPARSITY ? 1.0f : 0.0f) +
                                   (vv[j] < -SPARSITY ? -1.0f : 0.0f));
        *(uint4*)(smem + k * 512 + ((nch ^ (k & 7)) << 4)) = *(const uint4*)h;
    }

    float acc[4][8][4] = {};
    float4 areg[2][2];

    auto ldgA = [&](int it) {
        const int k0 = it * TK;
        #pragma unroll
        for (int s = 0; s < 2; s++) {
            int m = t + 256 * s;
            int r = m >> 2, c = m & 3;
            const float* p = x + (size_t)(bm + r) * lda + k0 + (c << 3);
            areg[s][0] = *(const float4*)p;
            areg[s][1] = *(const float4*)(p + 4);
        }
    };
    auto stsA = [&](int slot) {
        #pragma unroll
        for (int s = 0; s < 2; s++) {
            int m = t + 256 * s;
            int r = m >> 2, c = m & 3;
            __half2 h[4];
            h[0] = __floats2half2_rn(areg[s][0].x, areg[s][0].y);
            h[1] = __floats2half2_rn(areg[s][0].z, areg[s][0].w);
            h[2] = __floats2half2_rn(areg[s][1].x, areg[s][1].y);
            h[3] = __floats2half2_rn(areg[s][1].z, areg[s][1].w);
            *(uint4*)(smem + G1_B + slot * A_TILE + swz16(r, c)) = *(const uint4*)h;
        }
    };

    ldgA(0);
    stsA(0);
    ldgA(1);
    __syncthreads();

    const int g = lane >> 3, l7 = lane & 7;
    const int KITERS = DIN / TK;   // 8

    for (int it = 0; it < KITERS; it++) {
        stsA((it + 1) & 1);
        ldgA(min(it + 2, KITERS - 1));

        const uint32_t abase = sA0 + (it & 1) * A_TILE;

        #pragma unroll
        for (int ks = 0; ks < 2; ks++) {
            uint32_t a[4][4];
            #pragma unroll
            for (int mf = 0; mf < 4; mf++) {
                int row = M0 + mf * 16 + ((g & 1) << 3) + l7;
                int ch  = ks * 2 + (g >> 1);
                ldsm4(a[mf][0], a[mf][1], a[mf][2], a[mf][3], abase + swz16(row, ch));
            }
            uint32_t bf[8][2];
            #pragma unroll
            for (int j8 = 0; j8 < 4; j8++) {
                int krow = it * TK + ks * 16 + ((g & 1) << 3) + l7;
                int nch  = ((N0 + j8 * 16) >> 3) + (g >> 1);
                uint32_t r0, r1, r2, r3;
                ldsm4t(r0, r1, r2, r3,
                       sb + krow * 512 + ((nch ^ (krow & 7)) << 4));
                bf[j8 * 2][0] = r0; bf[j8 * 2][1] = r1;
                bf[j8 * 2 + 1][0] = r2; bf[j8 * 2 + 1][1] = r3;
            }
            #pragma unroll
            for (int mf = 0; mf < 4; mf++)
                #pragma unroll
                for (int nf = 0; nf < 8; nf++)
                    mma_f16(acc[mf][nf], a[mf][0], a[mf][1], a[mf][2], a[mf][3],
                            bf[nf][0], bf[nf][1]);
        }
        __syncthreads();
    }

    const int rq = lane >> 2, cq = lane & 3;
    #pragma unroll
    for (int nf = 0; nf < 8; nf++) {
        const int col = N0 + nf * 8 + (cq << 1);
        #pragma unroll
        for (int mf = 0; mf < 4; mf++) {
            const int row = bm + M0 + mf * 16 + rq;
            __half* o0 = SUP + (size_t)row * ldc + col;
            *(__half2*)o0 =
                __floats2half2_rn(acc[mf][nf][0] * SPARSITY,
                                  acc[mf][nf][1] * SPARSITY);
            *(__half2*)(o0 + 8 * (size_t)ldc) =
                __floats2half2_rn(acc[mf][nf][2] * SPARSITY,
                                  acc[mf][nf][3] * SPARSITY);
        }
    }
}

// ============================================================================
extern "C" void kernel_launch(void* const* d_in, const int* in_sizes, int n_in,
                              void* d_out, int out_size) {
    const float* x      = (const float*)d_in[0];
    const float* adj    = (const float*)d_in[1];
    const float* weight = (const float*)d_in[2];
    const float* bias   = (const float*)d_in[3];
    float* out = (float*)d_out;

    __half* SUP;
    cudaGetSymbolAddress((void**)&SUP, g_SUP);

    // 1) SUP = (x @ quantize(W)) * s  (quantization fused, no prep kernel)
    {
        cudaFuncSetAttribute(gemm1_kernel,
                             cudaFuncAttributeMaxDynamicSharedMemorySize, G1_SM);
        gemm1_kernel<<<(BATCH * NN) / 128, 256, G1_SM>>>(x, DIN, weight, DOUT,
                                                         SUP, DOUT);
    }
    // 2) out[b] = relu(adj[b] @ SUP[b] + bias)  (round-9 codegen, untouched)
    {
        auto k = mm_kernel<NN / TK, true, true>;
        cudaFuncSetAttribute(k, cudaFuncAttributeMaxDynamicSharedMemorySize, G_SM);
        dim3 grid(NN / 128, BATCH, 1);
        k<<<grid, 256, G_SM>>>(
            adj, (size_t)NN * NN, NN,
            SUP, (size_t)NN * DOUT, DOUT,
            out, (size_t)NN * DOUT, DOUT,
            bias);
    }
}

// round 15
// speedup vs baseline: 1.4229x; 1.0283x over previous
#include <cuda_runtime.h>
#include <cuda_fp16.h>
#include <cstdint>

#define SPARSITY 0.01f
#define BATCH 8
#define NN    2048
#define DIN   256
#define DOUT  256

__device__ __half g_SUP[BATCH * NN * DOUT];  // support fp16: [b*node][col]
__device__ unsigned g_bar = 0;               // grid barrier (self-resetting)
__device__ unsigned g_fin = 0;

__device__ __forceinline__ uint32_t smem_u32(const void* p) {
    uint32_t a;
    asm("{ .reg .u64 t; cvta.to.shared.u64 t, %1; cvt.u32.u64 %0, t; }"
        : "=r"(a) : "l"(p));
    return a;
}

#define TK 32
__device__ __forceinline__ uint32_t swz16(int row, int c) {
    return (uint32_t)(row * 64 + ((c ^ ((row >> 1) & 3)) << 4));
}
__device__ __forceinline__ void ldsm4(uint32_t& r0, uint32_t& r1, uint32_t& r2,
                                      uint32_t& r3, uint32_t addr) {
    asm volatile("ldmatrix.sync.aligned.m8n8.x4.shared.b16 {%0,%1,%2,%3}, [%4];"
                 : "=r"(r0), "=r"(r1), "=r"(r2), "=r"(r3) : "r"(addr));
}
__device__ __forceinline__ void ldsm4t(uint32_t& r0, uint32_t& r1, uint32_t& r2,
                                       uint32_t& r3, uint32_t addr) {
    asm volatile("ldmatrix.sync.aligned.m8n8.x4.trans.shared.b16 {%0,%1,%2,%3}, [%4];"
                 : "=r"(r0), "=r"(r1), "=r"(r2), "=r"(r3) : "r"(addr));
}
__device__ __forceinline__ void mma_f16(float* d, uint32_t a0, uint32_t a1,
                                        uint32_t a2, uint32_t a3,
                                        uint32_t b0, uint32_t b1) {
    asm volatile(
        "mma.sync.aligned.m16n8k16.row.col.f32.f16.f16.f32 "
        "{%0,%1,%2,%3}, {%4,%5,%6,%7}, {%8,%9}, {%0,%1,%2,%3};"
        : "+f"(d[0]), "+f"(d[1]), "+f"(d[2]), "+f"(d[3])
        : "r"(a0), "r"(a1), "r"(a2), "r"(a3), "r"(b0), "r"(b1));
}
__device__ __forceinline__ void cpasync16(uint32_t dst, const void* src) {
    asm volatile("cp.async.cg.shared.global [%0], [%1], 16;" :: "r"(dst), "l"(src));
}

#define B_STAGE  16384
#define A_TILE   8192
#define WQ_BYTES (DIN * 512)                  // 131072: quant(W) trans-ldsm layout
#define SM_TOTAL (WQ_BYTES + 2 * A_TILE)      // 147456 (phase 2 needs only 81920)

// ============================================================================
// Persistent fused kernel, grid = 128 CTAs (all resident: 1 CTA/SM, 128<148).
// Phase 1: SUP = (x @ quantize(W)) * s          (M=16384, N=256, K=256)
// Grid barrier (atomics, self-resetting)
// Phase 2: out[b] = relu(adj[b] @ SUP[b] + bias) (M=2048, N=256, K=2048/batch)
// Runtime strides everywhere — constant-folding them regresses codegen (R11).
// ============================================================================
__global__ void __launch_bounds__(256, 1) fused_kernel(
    const float* __restrict__ x,   int ldx,
    const float* __restrict__ adj, size_t strideAdj, int lda2,
    const float* __restrict__ W,   int ldw,
    const float* __restrict__ bias,
    float* __restrict__ out,       size_t strideOut, int ldo,
    __half* __restrict__ SUP,      size_t strideSup, int ldsup,
    int nblocks)
{
    extern __shared__ char smem[];
    const uint32_t sb = smem_u32(smem);
    const int t = threadIdx.x, wid = t >> 5, lane = t & 31;
    const int g = lane >> 3, l7 = lane & 7;
    const int M0 = (wid & 1) * 64;
    const int N0 = (wid >> 1) * 64;
    const int rq = lane >> 2, cq = lane & 3;

    float acc[4][8][4];
    float4 areg[2][2];

    // ======================= PHASE 1 =======================
    {
        const int bm = blockIdx.x * 128;

        auto ldgA = [&](int it) {
            const int k0 = it * TK;
            #pragma unroll
            for (int s = 0; s < 2; s++) {
                int m = t + 256 * s;
                int r = m >> 2, c = m & 3;
                const float* p = x + (size_t)(bm + r) * ldx + k0 + (c << 3);
                areg[s][0] = *(const float4*)p;
                areg[s][1] = *(const float4*)(p + 4);
            }
        };
        auto stsA = [&](int slot) {
            #pragma unroll
            for (int s = 0; s < 2; s++) {
                int m = t + 256 * s;
                int r = m >> 2, c = m & 3;
                __half2 h[4];
                h[0] = __floats2half2_rn(areg[s][0].x, areg[s][0].y);
                h[1] = __floats2half2_rn(areg[s][0].z, areg[s][0].w);
                h[2] = __floats2half2_rn(areg[s][1].x, areg[s][1].y);
                h[3] = __floats2half2_rn(areg[s][1].z, areg[s][1].w);
                *(uint4*)(smem + WQ_BYTES + slot * A_TILE + swz16(r, c)) =
                    *(const uint4*)h;
            }
        };

        ldgA(0);   // issue A loads BEFORE W build so both latency chains overlap

        // build quant(W) in smem, trans-ldsm layout
        #pragma unroll 4
        for (int c = t; c < 8192; c += 256) {      // 16B fp16 chunks
            int k = c >> 5, nch = c & 31;
            const float* p = W + (size_t)k * ldw + (nch << 3);
            float4 v0 = *(const float4*)p;
            float4 v1 = *(const float4*)(p + 4);
            float vv[8] = {v0.x, v0.y, v0.z, v0.w, v1.x, v1.y, v1.z, v1.w};
            __half h[8];
            #pragma unroll
            for (int j = 0; j < 8; j++)
                h[j] = __float2half_rn((vv[j] > SPARSITY ? 1.0f : 0.0f) +
                                       (vv[j] < -SPARSITY ? -1.0f : 0.0f));
            *(uint4*)(smem + k * 512 + ((nch ^ (k & 7)) << 4)) = *(const uint4*)h;
        }

        #pragma unroll
        for (int mf = 0; mf < 4; mf++)
            #pragma unroll
            for (int nf = 0; nf < 8; nf++)
                #pragma unroll
                for (int q = 0; q < 4; q++) acc[mf][nf][q] = 0.0f;

        stsA(0);
        ldgA(1);
        __syncthreads();

        const int KITERS = DIN / TK;   // 8
        for (int it = 0; it < KITERS; it++) {
            stsA((it + 1) & 1);
            ldgA(min(it + 2, KITERS - 1));

            const uint32_t abase = sb + WQ_BYTES + (it & 1) * A_TILE;

            #pragma unroll
            for (int ks = 0; ks < 2; ks++) {
                uint32_t a[4][4];
                #pragma unroll
                for (int mf = 0; mf < 4; mf++) {
                    int row = M0 + mf * 16 + ((g & 1) << 3) + l7;
                    int ch  = ks * 2 + (g >> 1);
                    ldsm4(a[mf][0], a[mf][1], a[mf][2], a[mf][3],
                          abase + swz16(row, ch));
                }
                uint32_t bf[8][2];
                #pragma unroll
                for (int j8 = 0; j8 < 4; j8++) {
                    int krow = it * TK + ks * 16 + ((g & 1) << 3) + l7;
                    int nch  = ((N0 + j8 * 16) >> 3) + (g >> 1);
                    uint32_t r0, r1, r2, r3;
                    ldsm4t(r0, r1, r2, r3,
                           sb + krow * 512 + ((nch ^ (krow & 7)) << 4));
                    bf[j8 * 2][0] = r0; bf[j8 * 2][1] = r1;
                    bf[j8 * 2 + 1][0] = r2; bf[j8 * 2 + 1][1] = r3;
                }
                #pragma unroll
                for (int mf = 0; mf < 4; mf++)
                    #pragma unroll
                    for (int nf = 0; nf < 8; nf++)
                        mma_f16(acc[mf][nf], a[mf][0], a[mf][1], a[mf][2], a[mf][3],
                                bf[nf][0], bf[nf][1]);
            }
            __syncthreads();
        }

        // epilogue: * SPARSITY -> fp16 SUP
        #pragma unroll
        for (int nf = 0; nf < 8; nf++) {
            const int col = N0 + nf * 8 + (cq << 1);
            #pragma unroll
            for (int mf = 0; mf < 4; mf++) {
                const int row = bm + M0 + mf * 16 + rq;
                __half* o0 = SUP + (size_t)row * ldsup + col;
                *(__half2*)o0 =
                    __floats2half2_rn(acc[mf][nf][0] * SPARSITY,
                                      acc[mf][nf][1] * SPARSITY);
                *(__half2*)(o0 + 8 * (size_t)ldsup) =
                    __floats2half2_rn(acc[mf][nf][2] * SPARSITY,
                                      acc[mf][nf][3] * SPARSITY);
            }
        }
    }

    // ======================= GRID BARRIER =======================
    __threadfence();
    __syncthreads();
    if (t == 0) {
        atomicAdd(&g_bar, 1u);
        while (*(volatile unsigned*)&g_bar < (unsigned)nblocks) {}
    }
    __syncthreads();
    __threadfence();

    // ======================= PHASE 2 =======================
    {
        const int b  = blockIdx.x >> 4;
        const int bm = (blockIdx.x & 15) * 128;

        const float*  Ag = adj + (size_t)b * strideAdj;
        const __half* Bg = SUP + (size_t)b * strideSup * NN / NN * 1;  // see below
        // (strideSup here is per-batch element stride of SUP = NN*DOUT)
        Bg = SUP + (size_t)b * (size_t)NN * DOUT;

        const uint32_t sB0 = sb;
        const uint32_t sA0 = sb + 4 * B_STAGE;

        #pragma unroll
        for (int mf = 0; mf < 4; mf++)
            #pragma unroll
            for (int nf = 0; nf < 8; nf++)
                #pragma unroll
                for (int q = 0; q < 4; q++) acc[mf][nf][q] = 0.0f;

        auto loadB = [&](int it, int slot) {
            const int k0 = it * TK;
            const uint32_t s0 = sB0 + slot * B_STAGE;
            #pragma unroll
            for (int i = 0; i < 4; i++) {
                int c = t + 256 * i;
                int k = c >> 5, nch = c & 31;
                cpasync16(s0 + k * 512 + ((nch ^ (k & 7)) << 4),
                          Bg + (size_t)(k0 + k) * ldsup + (nch << 3));
            }
            asm volatile("cp.async.commit_group;");
        };
        auto ldgA = [&](int it) {
            const int k0 = it * TK;
            #pragma unroll
            for (int s = 0; s < 2; s++) {
                int m = t + 256 * s;
                int r = m >> 2, c = m & 3;
                const float* p = Ag + (size_t)(bm + r) * lda2 + k0 + (c << 3);
                areg[s][0] = *(const float4*)p;
                areg[s][1] = *(const float4*)(p + 4);
            }
        };
        auto stsA = [&](int slot) {
            #pragma unroll
            for (int s = 0; s < 2; s++) {
                int m = t + 256 * s;
                int r = m >> 2, c = m & 3;
                __half2 h[4];
                h[0] = __floats2half2_rn(areg[s][0].x, areg[s][0].y);
                h[1] = __floats2half2_rn(areg[s][0].z, areg[s][0].w);
                h[2] = __floats2half2_rn(areg[s][1].x, areg[s][1].y);
                h[3] = __floats2half2_rn(areg[s][1].z, areg[s][1].w);
                *(uint4*)(smem + 4 * B_STAGE + slot * A_TILE + swz16(r, c)) =
                    *(const uint4*)h;
            }
        };

        ldgA(0);
        loadB(0, 0);
        loadB(1, 1);
        loadB(2, 2);
        stsA(0);
        ldgA(1);
        asm volatile("cp.async.wait_group 2;");
        __syncthreads();

        const int KITERS = NN / TK;   // 64
        for (int it = 0; it < KITERS; it++) {
            if (it + 3 < KITERS) loadB(it + 3, (it + 3) & 3);
            else asm volatile("cp.async.commit_group;");

            stsA((it + 1) & 1);
            ldgA(min(it + 2, KITERS - 1));

            const uint32_t abase = sA0 + (it & 1) * A_TILE;
            const uint32_t bbase = sB0 + (it & 3) * B_STAGE;

            #pragma unroll
            for (int ks = 0; ks < 2; ks++) {
                uint32_t a[4][4];
                #pragma unroll
                for (int mf = 0; mf < 4; mf++) {
                    int row = M0 + mf * 16 + ((g & 1) << 3) + l7;
                    int ch  = ks * 2 + (g >> 1);
                    ldsm4(a[mf][0], a[mf][1], a[mf][2], a[mf][3],
                          abase + swz16(row, ch));
                }
                uint32_t bf[8][2];
                #pragma unroll
                for (int j8 = 0; j8 < 4; j8++) {
                    int kl  = ks * 16 + ((g & 1) << 3) + l7;
                    int nch = ((N0 + j8 * 16) >> 3) + (g >> 1);
                    uint32_t r0, r1, r2, r3;
                    ldsm4t(r0, r1, r2, r3,
                           bbase + kl * 512 + ((nch ^ (kl & 7)) << 4));
                    bf[j8 * 2][0] = r0; bf[j8 * 2][1] = r1;
                    bf[j8 * 2 + 1][0] = r2; bf[j8 * 2 + 1][1] = r3;
                }
                #pragma unroll
                for (int mf = 0; mf < 4; mf++)
                    #pragma unroll
                    for (int nf = 0; nf < 8; nf++)
                        mma_f16(acc[mf][nf], a[mf][0], a[mf][1], a[mf][2], a[mf][3],
                                bf[nf][0], bf[nf][1]);
            }

            asm volatile("cp.async.wait_group 2;");
            __syncthreads();
        }

        // epilogue: bias + relu, fp32 out
        float* Cg = out + (size_t)b * strideOut;
        #pragma unroll
        for (int nf = 0; nf < 8; nf++) {
            const int col = N0 + nf * 8 + (cq << 1);
            const float2 bv = *(const float2*)(bias + col);
            #pragma unroll
            for (int mf = 0; mf < 4; mf++) {
                const int row = bm + M0 + mf * 16 + rq;
                float* o0 = Cg + (size_t)row * ldo + col;
                float2 v0, v1;
                v0.x = fmaxf(acc[mf][nf][0] + bv.x, 0.0f);
                v0.y = fmaxf(acc[mf][nf][1] + bv.y, 0.0f);
                v1.x = fmaxf(acc[mf][nf][2] + bv.x, 0.0f);
                v1.y = fmaxf(acc[mf][nf][3] + bv.y, 0.0f);
                *(float2*)o0 = v0;
                *(float2*)(o0 + 8 * (size_t)ldo) = v1;
            }
        }
    }

    // ======================= RESET (for next graph replay) ==================
    __syncthreads();
    if (t == 0) {
        unsigned old = atomicAdd(&g_fin, 1u);
        if (old == (unsigned)nblocks - 1u) {   // last CTA out: nobody spins after
            atomicExch(&g_bar, 0u);
            atomicExch(&g_fin, 0u);
        }
    }
}

// ============================================================================
extern "C" void kernel_launch(void* const* d_in, const int* in_sizes, int n_in,
                              void* d_out, int out_size) {
    const float* x      = (const float*)d_in[0];  // [16384, 256]
    const float* adj    = (const float*)d_in[1];  // [8, 2048, 2048]
    const float* weight = (const float*)d_in[2];  // [256, 256]
    const float* bias   = (const float*)d_in[3];  // [256]
    float* out = (float*)d_out;                   // [8, 2048, 256]

    __half* SUP;
    cudaGetSymbolAddress((void**)&SUP, g_SUP);

    cudaFuncSetAttribute(fused_kernel,
                         cudaFuncAttributeMaxDynamicSharedMemorySize, SM_TOTAL);
    fused_kernel<<<128, 256, SM_TOTAL>>>(
        x, DIN,
        adj, (size_t)NN * NN, NN,
        weight, DOUT,
        bias,
        out, (size_t)NN * DOUT, DOUT,
        SUP, (size_t)NN * DOUT, DOUT,
        128);
}